// round 12
// baseline (speedup 1.0000x reference)
#include <cuda_runtime.h>
#include <cuda_bf16.h>
#include <math.h>
#include <stdint.h>

// Problem dims (fixed by the reference)
#define NTOK   4096      // B*T = 2*2048
#define SEQ    2048
#define BATCH  2
#define DMODEL 1024
#define NH     16
#define HDIM   64
#define FFDIM  4096
#define QKVW   3072      // 3*DMODEL
#define NQT    (SEQ / 128)   // 16 query tiles per batch-head

// tcgen05 only exists in the arch-specific (sm_103a / sm_103f) compilation pass.
#if defined(__CUDA_ARCH__) && (__CUDA_ARCH__ == 1030) && \
    (defined(__CUDA_ARCH_FEAT_SM103_ALL) || defined(__CUDA_ARCH_SPECIFIC__) || \
     defined(__CUDA_ARCH_FAMILY_SPECIFIC__))
#define HAS_TCGEN05 1
#else
#define HAS_TCGEN05 0
#endif

// cp.async works on all passes (sm_80+)
#define CP_ASYNC16(smem_u32, gptr) \
    asm volatile("cp.async.cg.shared.global [%0], [%1], 16;" \
                 :: "r"((uint32_t)(smem_u32)), "l"(gptr) : "memory")
#define CP_COMMIT() asm volatile("cp.async.commit_group;" ::: "memory")
#define CP_WAIT_0() asm volatile("cp.async.wait_group 0;" ::: "memory")
#define CP_WAIT_1() asm volatile("cp.async.wait_group 1;" ::: "memory")

__device__ __forceinline__ uint32_t smem_u32_of(const void* p) {
    uint32_t a;
    asm("{ .reg .u64 t; cvta.to.shared.u64 t, %1; cvt.u32.u64 %0, t; }" : "=r"(a) : "l"(p));
    return a;
}

#if HAS_TCGEN05
// ======================= PTX helpers (arch-specific pass only) =======================
__device__ __forceinline__ uint32_t elect_one_pred() {
    uint32_t pred;
    asm volatile("{\n\t.reg .pred p;\n\telect.sync _|p, 0xFFFFFFFF;\n\tselp.b32 %0, 1, 0, p;\n\t}"
                 : "=r"(pred));
    return pred;
}

static constexpr uint64_t SMEM_DESC_BASE_SW128 =
    (uint64_t(2) << 61) | (uint64_t(1) << 46) | (uint64_t(64) << 32) | (uint64_t(1) << 16);
#define MAKE_SMEM_DESC(base_addr) \
    (SMEM_DESC_BASE_SW128 | ((uint64_t)((base_addr) >> 4) & 0x3FFF))

#define TCGEN05_ALLOC(sa, n) \
    asm volatile("tcgen05.alloc.cta_group::1.sync.aligned.shared::cta.b32 [%0], %1;" \
                 :: "r"((uint32_t)(sa)), "r"((uint32_t)(n)) : "memory")
#define TCGEN05_DEALLOC(t, n) \
    asm volatile("tcgen05.dealloc.cta_group::1.sync.aligned.b32 %0, %1;" :: "r"(t), "r"((uint32_t)(n)))
#define TCGEN05_RELINQUISH() \
    asm volatile("tcgen05.relinquish_alloc_permit.cta_group::1.sync.aligned;")
#define TCGEN05_COMMIT(mb) \
    asm volatile("tcgen05.commit.cta_group::1.mbarrier::arrive::one.shared::cluster.b64 [%0];" \
                 :: "r"((uint32_t)(mb)) : "memory")
#define TCGEN05_FENCE_AFTER() asm volatile("tcgen05.fence::after_thread_sync;" ::: "memory")
#define TCGEN05_WAIT_LD() asm volatile("tcgen05.wait::ld.sync.aligned;" ::: "memory")
#define FENCE_PROXY_ASYNC() asm volatile("fence.proxy.async.shared::cta;" ::: "memory")

#define MBARRIER_INIT(mb, cnt) \
    asm volatile("mbarrier.init.shared.b64 [%0], %1;" :: "r"((uint32_t)(mb)), "r"((uint32_t)(cnt)) : "memory")

#define MBARRIER_WAIT_PARITY(mb, par) do { \
    uint32_t _mb = (uint32_t)(mb), _p = (uint32_t)(par), _d; \
    asm volatile("{\n\t.reg .pred p;\n\t" \
        "mbarrier.try_wait.parity.acquire.cta.shared::cta.b64 p, [%1], %2;\n\t" \
        "selp.b32 %0, 1, 0, p;\n\t}" : "=r"(_d) : "r"(_mb), "r"(_p) : "memory"); \
    if (!_d) { \
        asm volatile("{\n\t.reg .pred P1;\n\t" \
            "WL_%=:\n\t" \
            "mbarrier.try_wait.parity.acquire.cta.shared::cta.b64 P1, [%0], %1, 0x989680;\n\t" \
            "@P1 bra.uni WD_%=;\n\t" \
            "bra.uni WL_%=;\n\t" \
            "WD_%=:\n\t}" :: "r"(_mb), "r"(_p) : "memory"); \
    } \
} while (0)

#define TCGEN05_LD_X32(r, ta) \
    asm volatile("tcgen05.ld.sync.aligned.32x32b.x32.b32 " \
        "{%0, %1, %2, %3, %4, %5, %6, %7, %8, %9, %10, %11, %12, %13, %14, %15, " \
        "%16, %17, %18, %19, %20, %21, %22, %23, %24, %25, %26, %27, %28, %29, %30, %31}, [%32];" \
        : "=r"((r)[0]), "=r"((r)[1]), "=r"((r)[2]), "=r"((r)[3]), \
          "=r"((r)[4]), "=r"((r)[5]), "=r"((r)[6]), "=r"((r)[7]), \
          "=r"((r)[8]), "=r"((r)[9]), "=r"((r)[10]), "=r"((r)[11]), \
          "=r"((r)[12]), "=r"((r)[13]), "=r"((r)[14]), "=r"((r)[15]), \
          "=r"((r)[16]), "=r"((r)[17]), "=r"((r)[18]), "=r"((r)[19]), \
          "=r"((r)[20]), "=r"((r)[21]), "=r"((r)[22]), "=r"((r)[23]), \
          "=r"((r)[24]), "=r"((r)[25]), "=r"((r)[26]), "=r"((r)[27]), \
          "=r"((r)[28]), "=r"((r)[29]), "=r"((r)[30]), "=r"((r)[31]) \
        : "r"(ta))

// cg1 kind::f16 SS-mode MMA (A and B both in SMEM, bf16 in / fp32 accum)
__device__ __forceinline__ void mma_f16_ss(uint32_t d, uint64_t ad, uint64_t bd,
                                           uint32_t idesc, bool acc) {
    uint32_t en = acc ? 1u : 0u;
    asm volatile(
        "{\n\t.reg .pred p;\n\tsetp.ne.u32 p, %5, 0;\n\t"
        "tcgen05.mma.cta_group::1.kind::f16 [%0], %1, %2, %3, {%4, %4, %4, %4}, p;\n\t}"
        :: "r"(d), "l"(ad), "l"(bd), "r"(idesc), "r"(0u), "r"(en) : "memory");
}

// idesc for attention MMAs: M=128, N=64, K-major both (validated in R4)
static constexpr uint32_t ATTN_IDESC =
    (1u << 4) | (1u << 7) | (1u << 10) | ((64u / 8u) << 17) | ((128u / 16u) << 24);
#endif  // HAS_TCGEN05

#define SMEM_SWIZZLE_128B(off) ((off) ^ (((off) >> 3) & 0x70))

// ======================= scratch (device globals) =======================
__device__ float g_x2  [NTOK * DMODEL];          // residual after attn proj
__device__ float g_Op  [2 * NTOK * DMODEL];      // split-KV partial O (fp32)
__device__ float g_lp  [2 * NTOK * NH];          // split-KV partial l
__device__ __nv_bfloat16 g_qkv_hi[NTOK * QKVW],  g_qkv_lo[NTOK * QKVW];
__device__ __nv_bfloat16 g_h_hi  [NTOK * DMODEL], g_h_lo  [NTOK * DMODEL];
__device__ __nv_bfloat16 g_attn_hi[NTOK * DMODEL], g_attn_lo[NTOK * DMODEL];
__device__ __nv_bfloat16 g_hh_hi [NTOK * DMODEL], g_hh_lo [NTOK * DMODEL];
__device__ __nv_bfloat16 g_ff_hi [NTOK * FFDIM],  g_ff_lo [NTOK * FFDIM];
__device__ __nv_bfloat16 g_WqkvT_hi[QKVW * DMODEL],  g_WqkvT_lo[QKVW * DMODEL];
__device__ __nv_bfloat16 g_WoT_hi [DMODEL * DMODEL], g_WoT_lo [DMODEL * DMODEL];
__device__ __nv_bfloat16 g_W1T_hi [FFDIM * DMODEL],  g_W1T_lo [FFDIM * DMODEL];
__device__ __nv_bfloat16 g_W2T_hi [DMODEL * FFDIM],  g_W2T_lo [DMODEL * FFDIM];

__device__ __forceinline__ void split_store(__nv_bfloat16* hi, __nv_bfloat16* lo,
                                            long ofs, float v) {
    __nv_bfloat16 h = __float2bfloat16(v);
    hi[ofs] = h;
    lo[ofs] = __float2bfloat16(v - __bfloat162float(h));
}
__device__ __forceinline__ uint32_t pack2bf(float a, float b) {
    __nv_bfloat162 t;
    t.x = __float2bfloat16(a);
    t.y = __float2bfloat16(b);
    return *(uint32_t*)&t;
}
__device__ __forceinline__ float gelu_exact(float x) {
    return 0.5f * x * (1.0f + erff(x * 0.70710678118654752f));
}

// ======================= LayerNorm -> bf16 hi/lo planes =======================
__global__ __launch_bounds__(256) void ln_kernel(const float* __restrict__ x,
                                                 const float* __restrict__ g,
                                                 const float* __restrict__ b,
                                                 __nv_bfloat16* __restrict__ yhi,
                                                 __nv_bfloat16* __restrict__ ylo)
{
    const int row = blockIdx.x;
    const int tid = threadIdx.x;
    const float* xr = x + (long)row * DMODEL;
    float4 v = *(const float4*)(xr + tid * 4);

    float s  = v.x + v.y + v.z + v.w;
    float sq = v.x*v.x + v.y*v.y + v.z*v.z + v.w*v.w;
    #pragma unroll
    for (int off = 16; off > 0; off >>= 1) {
        s  += __shfl_xor_sync(0xffffffffu, s,  off);
        sq += __shfl_xor_sync(0xffffffffu, sq, off);
    }
    __shared__ float reds[8], redq[8];
    const int wid = tid >> 5;
    if ((tid & 31) == 0) { reds[wid] = s; redq[wid] = sq; }
    __syncthreads();
    float st = 0.f, qt = 0.f;
    #pragma unroll
    for (int w = 0; w < 8; w++) { st += reds[w]; qt += redq[w]; }

    const float mu   = st * (1.0f / DMODEL);
    const float var  = qt * (1.0f / DMODEL) - mu * mu;
    const float rstd = rsqrtf(var + 1e-5f);

    float4 gv = *(const float4*)(g + tid * 4);
    float4 bv = *(const float4*)(b + tid * 4);
    float o0 = (v.x - mu) * rstd * gv.x + bv.x;
    float o1 = (v.y - mu) * rstd * gv.y + bv.y;
    float o2 = (v.z - mu) * rstd * gv.z + bv.z;
    float o3 = (v.w - mu) * rstd * gv.w + bv.w;
    const long base = (long)row * DMODEL + tid * 4;
    split_store(yhi, ylo, base + 0, o0);
    split_store(yhi, ylo, base + 1, o1);
    split_store(yhi, ylo, base + 2, o2);
    split_store(yhi, ylo, base + 3, o3);
}

// ============== weight transpose + bf16 hi/lo: W[K,N] -> T[N,K] (coalesced) ==============
__global__ __launch_bounds__(256) void wtrans_kernel(const float* __restrict__ W,
                                                     __nv_bfloat16* __restrict__ Thi,
                                                     __nv_bfloat16* __restrict__ Tlo,
                                                     int K, int N)
{
    __shared__ float tile[64][65];
    const int nb = blockIdx.x * 64;
    const int kb = blockIdx.y * 64;
    const int tid = threadIdx.x;
    #pragma unroll
    for (int i = 0; i < 4; i++) {
        const int idx = tid + i * 256;       // 0..1023
        const int k = idx >> 4;
        const int n4 = (idx & 15) << 2;
        float4 v = *(const float4*)&W[(long)(kb + k) * N + nb + n4];
        tile[k][n4 + 0] = v.x;
        tile[k][n4 + 1] = v.y;
        tile[k][n4 + 2] = v.z;
        tile[k][n4 + 3] = v.w;
    }
    __syncthreads();
    #pragma unroll
    for (int i = 0; i < 4; i++) {
        const int idx = tid + i * 256;       // 0..1023
        const int n  = idx >> 4;
        const int kq = (idx & 15) << 2;      // 4 consecutive K per thread
        float v0 = tile[kq + 0][n], v1 = tile[kq + 1][n];
        float v2 = tile[kq + 2][n], v3 = tile[kq + 3][n];
        const long ofs = (long)(nb + n) * K + kb + kq;
        uint2 hp, lp;
        hp.x = pack2bf(v0, v1); hp.y = pack2bf(v2, v3);
        __nv_bfloat162* h01 = (__nv_bfloat162*)&hp.x;
        __nv_bfloat162* h23 = (__nv_bfloat162*)&hp.y;
        lp.x = pack2bf(v0 - __bfloat162float(h01->x), v1 - __bfloat162float(h01->y));
        lp.y = pack2bf(v2 - __bfloat162float(h23->x), v3 - __bfloat162float(h23->y));
        *(uint2*)(Thi + ofs) = hp;
        *(uint2*)(Tlo + ofs) = lp;
    }
}

// ======================= GEMM (templated tile-N, cp.async pipeline) =======================
// C[M,N] = A[M,K] @ B[N,K]^T, bf16 hi/lo planes (K-major).
// TILE_N = 256 -> 2 stages; TILE_N = 128 -> 3 stages.
// OP: 1 = +bias, GELU -> bf16 hi/lo ; 2 = +bias +res -> fp32 ; 3 = +bias -> bf16 hi/lo
#define SM_TMEMPTR 0
#define SM_MBAR    16
#define SM_TILES   1024
#define GEMM_SMEM  197632      // 1024 + max(2*98304, 3*65536)

template<int OP, int TILE_N>
__global__ __launch_bounds__(256, 1) void gemm_tc(
    const __nv_bfloat16* __restrict__ Ahi, const __nv_bfloat16* __restrict__ Alo,
    const __nv_bfloat16* __restrict__ Bhi, const __nv_bfloat16* __restrict__ Blo,
    const float* __restrict__ bias, const float* __restrict__ res,
    float* __restrict__ Cf,
    __nv_bfloat16* __restrict__ Chi, __nv_bfloat16* __restrict__ Clo,
    int N, int K)
{
    extern __shared__ __align__(1024) char smem[];
    const int tid = threadIdx.x;
    const int mBase = blockIdx.y * 128;
    const int nBase = blockIdx.x * TILE_N;

    constexpr int NS = (TILE_N == 256) ? 2 : 3;
    constexpr int ST_AHI = 0;
    constexpr int ST_ALO = 16384;
    constexpr int ST_BHI = 32768;
    constexpr int ST_BLO = 32768 + TILE_N * 128;
    constexpr int STAGE_B = 32768 + TILE_N * 256;

#if HAS_TCGEN05
    const uint32_t smem_base = smem_u32_of(smem);
    const int wid = tid >> 5;
    const int lid = tid & 31;
    constexpr uint32_t IDESC =
        (1u << 4) | (1u << 7) | (1u << 10) | ((TILE_N / 8u) << 17) | (8u << 24);

    if (wid == 0) {
        TCGEN05_ALLOC(smem_base + SM_TMEMPTR, TILE_N);
        TCGEN05_RELINQUISH();
    }
    if (tid == 0) {
        #pragma unroll
        for (int i = 0; i < NS; i++)
            MBARRIER_INIT(smem_base + SM_MBAR + i * 8, 1);
    }
    __syncthreads();
    uint32_t tmem;
    asm volatile("ld.shared.b32 %0, [%1];" : "=r"(tmem) : "r"(smem_base + SM_TMEMPTR));

    auto load_chunk = [&](int c, int s) {
        const int k0 = c << 6;
        const __nv_bfloat16* srcAh = Ahi + (long)mBase * K + k0;
        const __nv_bfloat16* srcAl = Alo + (long)mBase * K + k0;
        const __nv_bfloat16* srcBh = Bhi + (long)nBase * K + k0;
        const __nv_bfloat16* srcBl = Blo + (long)nBase * K + k0;
        const uint32_t stage = smem_base + SM_TILES + s * STAGE_B;
        #pragma unroll
        for (int i = 0; i < 4; i++) {              // A: 128 rows
            const int idx = tid + i * 256;
            const int r   = idx >> 3;
            const int c16 = idx & 7;
            const long gofs = (long)r * K + (c16 << 3);
            const uint32_t sofs = stage + SMEM_SWIZZLE_128B((r << 7) | (c16 << 4));
            CP_ASYNC16(sofs + ST_AHI, srcAh + gofs);
            CP_ASYNC16(sofs + ST_ALO, srcAl + gofs);
        }
        #pragma unroll
        for (int i = 0; i < TILE_N / 32; i++) {    // B: TILE_N rows
            const int idx = tid + i * 256;
            const int r   = idx >> 3;
            const int c16 = idx & 7;
            const long gofs = (long)r * K + (c16 << 3);
            const uint32_t sofs = stage + SMEM_SWIZZLE_128B((r << 7) | (c16 << 4));
            CP_ASYNC16(sofs + ST_BHI, srcBh + gofs);
            CP_ASYNC16(sofs + ST_BLO, srcBl + gofs);
        }
        CP_COMMIT();
    };

    const int NC = K >> 6;   // K-chunks of 64 (>= 16 here)
    load_chunk(0, 0);
    load_chunk(1, 1);

    for (int c = 0; c < NC; c++) {
        const int s = c % NS;
        if (c + 1 < NC) CP_WAIT_1(); else CP_WAIT_0();
        FENCE_PROXY_ASYNC();
        __syncthreads();

        if (wid == 0) {
            const uint32_t stage = smem_base + SM_TILES + s * STAGE_B;
            const uint64_t dAhi = MAKE_SMEM_DESC(stage + ST_AHI);
            const uint64_t dAlo = MAKE_SMEM_DESC(stage + ST_ALO);
            const uint64_t dBhi = MAKE_SMEM_DESC(stage + ST_BHI);
            const uint64_t dBlo = MAKE_SMEM_DESC(stage + ST_BLO);
            if (elect_one_pred()) {
                #pragma unroll
                for (int kk = 0; kk < 4; kk++) {
                    mma_f16_ss(tmem, dAhi + kk * 2, dBhi + kk * 2, IDESC,
                               !(c == 0 && kk == 0));
                    mma_f16_ss(tmem, dAlo + kk * 2, dBhi + kk * 2, IDESC, true);
                    mma_f16_ss(tmem, dAhi + kk * 2, dBlo + kk * 2, IDESC, true);
                }
                TCGEN05_COMMIT(smem_base + SM_MBAR + s * 8);
            }
        }

        // prefetch chunk c+2 into stage (c+2)%NS (held chunk c+2-NS -> wait its MMA)
        if (c + 2 < NC) {
            const int prev = c + 2 - NS;
            if (prev >= 0)
                MBARRIER_WAIT_PARITY(smem_base + SM_MBAR + (prev % NS) * 8,
                                     ((prev / NS) & 1));
            load_chunk(c + 2, (c + 2) % NS);
        }
    }

    // wait for ALL MMAs (in-order pipe: last commit covers all prior)
    MBARRIER_WAIT_PARITY(smem_base + SM_MBAR + ((NC - 1) % NS) * 8, ((NC - 1) / NS) & 1);
    TCGEN05_FENCE_AFTER();

    // Epilogue: TILE_N/128 column-halves through the SMEM staging buffer
    float* sout = (float*)(smem + SM_TILES);
    #pragma unroll
    for (int h2 = 0; h2 < TILE_N / 128; h2++) {
        if (wid < 4) {
            const int r = (wid << 5) + lid;
            #pragma unroll
            for (int cb = 0; cb < 4; cb++) {
                uint32_t regs[32];
                TCGEN05_LD_X32(regs, tmem + h2 * 128 + (cb << 5));
                TCGEN05_WAIT_LD();
                #pragma unroll
                for (int j = 0; j < 32; j += 4) {
                    float4 v = make_float4(__uint_as_float(regs[j]),
                                           __uint_as_float(regs[j + 1]),
                                           __uint_as_float(regs[j + 2]),
                                           __uint_as_float(regs[j + 3]));
                    *(float4*)&sout[r * 132 + (cb << 5) + j] = v;
                }
            }
        }
        __syncthreads();

        for (int idx = tid; idx < 128 * 32; idx += 256) {
            const int r = idx >> 5;
            const int cc = (idx & 31) << 2;
            float4 v = *(float4*)&sout[r * 132 + cc];
            const long gr = mBase + r;
            const int  gc = nBase + h2 * 128 + cc;
            float4 bb = *(const float4*)&bias[gc];
            v.x += bb.x; v.y += bb.y; v.z += bb.z; v.w += bb.w;
            if (OP == 1 || OP == 3) {
                if (OP == 1) {
                    v.x = gelu_exact(v.x); v.y = gelu_exact(v.y);
                    v.z = gelu_exact(v.z); v.w = gelu_exact(v.w);
                }
                const long o = gr * N + gc;
                split_store(Chi, Clo, o + 0, v.x);
                split_store(Chi, Clo, o + 1, v.y);
                split_store(Chi, Clo, o + 2, v.z);
                split_store(Chi, Clo, o + 3, v.w);
            } else if (OP == 2) {
                float4 rr = *(const float4*)&res[gr * N + gc];
                v.x += rr.x; v.y += rr.y; v.z += rr.z; v.w += rr.w;
                *(float4*)&Cf[gr * N + gc] = v;
            } else {
                *(float4*)&Cf[gr * N + gc] = v;
            }
        }
        __syncthreads();
    }
    if (wid == 0) TCGEN05_DEALLOC(tmem, TILE_N);

#else  // =================== FFMA fallback (non-103a passes; never runs on GB300) ===================
    float* As = (float*)smem;                 // [8][128]
    float* Bs = As + 8 * 128;                 // [8][128]

    const int tx = tid & 15;
    const int ty = tid >> 4;
    const int row  = tid >> 1;                // 0..127
    const int kc   = (tid & 1) << 2;          // 0 or 4

    for (int h2 = 0; h2 < TILE_N / 128; h2++) {
        const int nB = nBase + h2 * 128;
        float acc[8][8];
        #pragma unroll
        for (int i = 0; i < 8; i++)
            #pragma unroll
            for (int j = 0; j < 8; j++) acc[i][j] = 0.f;

        for (int k0 = 0; k0 < K; k0 += 8) {
            {
                const long o = (long)(mBase + row) * K + k0 + kc;
                ushort4 h = *(const ushort4*)(Ahi + o);
                ushort4 l = *(const ushort4*)(Alo + o);
                As[(kc + 0) * 128 + row] = __bfloat162float(*(__nv_bfloat16*)&h.x) + __bfloat162float(*(__nv_bfloat16*)&l.x);
                As[(kc + 1) * 128 + row] = __bfloat162float(*(__nv_bfloat16*)&h.y) + __bfloat162float(*(__nv_bfloat16*)&l.y);
                As[(kc + 2) * 128 + row] = __bfloat162float(*(__nv_bfloat16*)&h.z) + __bfloat162float(*(__nv_bfloat16*)&l.z);
                As[(kc + 3) * 128 + row] = __bfloat162float(*(__nv_bfloat16*)&h.w) + __bfloat162float(*(__nv_bfloat16*)&l.w);
            }
            {
                const long o = (long)(nB + row) * K + k0 + kc;
                ushort4 h = *(const ushort4*)(Bhi + o);
                ushort4 l = *(const ushort4*)(Blo + o);
                Bs[(kc + 0) * 128 + row] = __bfloat162float(*(__nv_bfloat16*)&h.x) + __bfloat162float(*(__nv_bfloat16*)&l.x);
                Bs[(kc + 1) * 128 + row] = __bfloat162float(*(__nv_bfloat16*)&h.y) + __bfloat162float(*(__nv_bfloat16*)&l.y);
                Bs[(kc + 2) * 128 + row] = __bfloat162float(*(__nv_bfloat16*)&h.z) + __bfloat162float(*(__nv_bfloat16*)&l.z);
                Bs[(kc + 3) * 128 + row] = __bfloat162float(*(__nv_bfloat16*)&h.w) + __bfloat162float(*(__nv_bfloat16*)&l.w);
            }
            __syncthreads();

            #pragma unroll
            for (int k = 0; k < 8; k++) {
                float a[8], bb[8];
                #pragma unroll
                for (int i = 0; i < 8; i++) a[i]  = As[k * 128 + ty * 8 + i];
                #pragma unroll
                for (int j = 0; j < 8; j++) bb[j] = Bs[k * 128 + tx * 8 + j];
                #pragma unroll
                for (int i = 0; i < 8; i++)
                    #pragma unroll
                    for (int j = 0; j < 8; j++)
                        acc[i][j] = fmaf(a[i], bb[j], acc[i][j]);
            }
            __syncthreads();
        }

        #pragma unroll
        for (int i = 0; i < 8; i++) {
            const long gr = mBase + ty * 8 + i;
            #pragma unroll
            for (int j = 0; j < 8; j++) {
                const int gc = nB + tx * 8 + j;
                float v = acc[i][j] + bias[gc];
                if (OP == 1) {
                    v = gelu_exact(v);
                    split_store(Chi, Clo, gr * N + gc, v);
                } else if (OP == 3) {
                    split_store(Chi, Clo, gr * N + gc, v);
                } else if (OP == 2) {
                    Cf[gr * N + gc] = v + res[gr * N + gc];
                } else {
                    Cf[gr * N + gc] = v;
                }
            }
        }
        __syncthreads();
    }
#endif
}

// ======================= tcgen05 causal flash attention (split-KV, fixed-max) =======================
// Grid.x = 2*NQT: bx -> (qt, split). Split s handles kt in [s*(qt+1), (s+1)*(qt+1))
// of the 2qt+2 64-key tiles (equal halves). Fixed-max softmax makes the combine
// exact: O = O0+O1, l = l0+l1. Partial O written fp32 to scratch; combine kernel
// normalizes and emits bf16 hi/lo.
#define A_TMEMPTR 0
#define A_MBAR0   8
#define A_MBAR1   16
#define A_SLS     1056          // float[256]
#define A_Q       3072          // hi 16K, lo at +16384
#define A_K       35840         // hi 8K, lo at +8192
#define A_VT      52224         // hi 8K, lo at +8192
#define A_P       68608         // hi 16K, lo at +16384 ; V staging: hi +0, lo +8192
#define ATTN_SMEM 101376
#define ATTN_M0   20.0f

#if HAS_TCGEN05
__device__ __forceinline__ void attn_issue_S(uint32_t tmem, uint32_t sb) {
    const uint64_t dQh = MAKE_SMEM_DESC(sb + A_Q);
    const uint64_t dQl = MAKE_SMEM_DESC(sb + A_Q + 16384);
    const uint64_t dKh = MAKE_SMEM_DESC(sb + A_K);
    const uint64_t dKl = MAKE_SMEM_DESC(sb + A_K + 8192);
    #pragma unroll
    for (int kk = 0; kk < 4; kk++) {
        mma_f16_ss(tmem, dQh + kk * 2, dKh + kk * 2, ATTN_IDESC, kk != 0);
        mma_f16_ss(tmem, dQl + kk * 2, dKh + kk * 2, ATTN_IDESC, true);
        mma_f16_ss(tmem, dQh + kk * 2, dKl + kk * 2, ATTN_IDESC, true);
    }
}
__device__ __forceinline__ void attn_issue_PV(uint32_t tmem, uint32_t sb, bool first) {
    const uint64_t dPh = MAKE_SMEM_DESC(sb + A_P);
    const uint64_t dPl = MAKE_SMEM_DESC(sb + A_P + 16384);
    const uint64_t dVh = MAKE_SMEM_DESC(sb + A_VT);
    const uint64_t dVl = MAKE_SMEM_DESC(sb + A_VT + 8192);
    #pragma unroll
    for (int kk = 0; kk < 4; kk++) {
        mma_f16_ss(tmem + 64, dPh + kk * 2, dVh + kk * 2, ATTN_IDESC, !(first && kk == 0));
        mma_f16_ss(tmem + 64, dPl + kk * 2, dVh + kk * 2, ATTN_IDESC, true);
        mma_f16_ss(tmem + 64, dPh + kk * 2, dVl + kk * 2, ATTN_IDESC, true);
    }
}
#endif

__global__ __launch_bounds__(256, 2) void attn_tc(
    const __nv_bfloat16* __restrict__ qkv_hi,
    const __nv_bfloat16* __restrict__ qkv_lo,
    float* __restrict__ Op,
    float* __restrict__ lp)
{
    extern __shared__ __align__(1024) char smem[];
    const int tid  = threadIdx.x;
    const int wid  = tid >> 5;
    const int lid  = tid & 31;
    const int bx   = blockIdx.x;                  // 0..2*NQT-1
    const int qt   = NQT - 1 - (bx >> 1);         // reversed: long CTAs first
    const int spl  = bx & 1;
    const int head = blockIdx.y;
    const int bat  = blockIdx.z;
    const long tok0 = (long)bat * SEQ;

#if HAS_TCGEN05
    const uint32_t sb = smem_u32_of(smem);
    float* sls = (float*)(smem + A_SLS);
    if (wid == 0) {
        TCGEN05_ALLOC(sb + A_TMEMPTR, 128);
        TCGEN05_RELINQUISH();
    }
    if (tid == 0) {
        MBARRIER_INIT(sb + A_MBAR0, 1);
        MBARRIER_INIT(sb + A_MBAR1, 1);
    }
    __syncthreads();
    uint32_t tmem;
    asm volatile("ld.shared.b32 %0, [%1];" : "=r"(tmem) : "r"(sb + A_TMEMPTR));

    const int kt0 = spl * (qt + 1);               // first tile of this split
    const int kt1 = kt0 + (qt + 1);               // one past last

    // Q tile (128 x 64 hi/lo) + K tile kt0 via cp.async
    #pragma unroll
    for (int i = 0; i < 4; i++) {
        const int idx = tid + i * 256;
        const int r = idx >> 3, c8 = idx & 7;
        const uint32_t sofs = SMEM_SWIZZLE_128B((r << 7) | (c8 << 4));
        const long gq = (tok0 + qt * 128 + r) * (long)QKVW + head * 64 + (c8 << 3);
        CP_ASYNC16(sb + A_Q + sofs,         qkv_hi + gq);
        CP_ASYNC16(sb + A_Q + 16384 + sofs, qkv_lo + gq);
    }
    #pragma unroll
    for (int i = 0; i < 2; i++) {
        const int idx = tid + i * 256;       // 0..511
        const int r = idx >> 3, c8 = idx & 7;
        const uint32_t sofs = SMEM_SWIZZLE_128B((r << 7) | (c8 << 4));
        const long gk = (tok0 + kt0 * 64 + r) * (long)QKVW + 1024 + head * 64 + (c8 << 3);
        CP_ASYNC16(sb + A_K + sofs,        qkv_hi + gk);
        CP_ASYNC16(sb + A_K + 8192 + sofs, qkv_lo + gk);
    }
    CP_COMMIT();
    CP_WAIT_0();
    FENCE_PROXY_ASYNC();
    __syncthreads();
    if (wid == 0 && elect_one_pred()) {
        attn_issue_S(tmem, sb);
        TCGEN05_COMMIT(sb + A_MBAR0);
    }

    const int half = wid >> 2;                 // column half (32 key-cols / 32 hd-cols)
    const int row  = ((wid & 3) << 5) + lid;   // q row
    const int grow = qt * 128 + row;
    const float SCL = 0.125f * 1.4426950408889634f;  // fold 1/sqrt(hd) * log2(e)

    float l = 0.f;

    for (int kt = kt0; kt < kt1; kt++) {
        const int it  = kt - kt0;
        const bool pre = (kt + 1 < kt1);

        // stage V(kt) into P region (PV(kt-1) done: mb1 waited at prior loop end)
        #pragma unroll
        for (int i = 0; i < 2; i++) {
            const int idx = tid + i * 256;
            const int r = idx >> 3, c8 = idx & 7;
            const uint32_t sofs = SMEM_SWIZZLE_128B((r << 7) | (c8 << 4));
            const long gv = (tok0 + kt * 64 + r) * (long)QKVW + 2048 + head * 64 + (c8 << 3);
            CP_ASYNC16(sb + A_P + sofs,        qkv_hi + gv);
            CP_ASYNC16(sb + A_P + 8192 + sofs, qkv_lo + gv);
        }
        CP_COMMIT();   // group V (every thread)

        // wait S(kt) -> K buffer free -> K(kt+1) prefetch by warp 0 only
        MBARRIER_WAIT_PARITY(sb + A_MBAR0, it & 1);
        TCGEN05_FENCE_AFTER();
        if (pre && wid == 0) {
            #pragma unroll
            for (int i = 0; i < 16; i++) {
                const int idx = lid + i * 32;      // 0..511
                const int r = idx >> 3, c8 = idx & 7;
                const uint32_t sofs = SMEM_SWIZZLE_128B((r << 7) | (c8 << 4));
                const long gk = (tok0 + (kt + 1) * 64 + r) * (long)QKVW + 1024 + head * 64 + (c8 << 3);
                CP_ASYNC16(sb + A_K + sofs,        qkv_hi + gk);
                CP_ASYNC16(sb + A_K + 8192 + sofs, qkv_lo + gk);
            }
            CP_COMMIT();   // group K (warp 0 threads only)
        }

        // pull this warp's 32 S columns
        uint32_t r0[32];
        TCGEN05_LD_X32(r0, tmem + half * 32);
        TCGEN05_WAIT_LD();

        // V staged complete (warp 0 may still have K in flight)
        if (pre && wid == 0) CP_WAIT_1(); else CP_WAIT_0();
        __syncthreads();   // S1: staged V visible

        // transpose staged V -> Vt[hd][key] (hi + lo)
        #pragma unroll
        for (int i = 0; i < 8; i++) {
            const int idx = tid + i * 256;        // 0..2047
            const int c  = idx & 63;              // hd
            const int kp = idx >> 6;              // key pair 0..31
            const int so0 = SMEM_SWIZZLE_128B(((2 * kp)     << 7) | (c << 1));
            const int so1 = SMEM_SWIZZLE_128B(((2 * kp + 1) << 7) | (c << 1));
            const int dd  = SMEM_SWIZZLE_128B((c << 7) | (kp << 2));
            uint32_t a = *(const uint16_t*)(smem + A_P + so0);
            uint32_t b = *(const uint16_t*)(smem + A_P + so1);
            *(uint32_t*)(smem + A_VT + dd) = a | (b << 16);
            a = *(const uint16_t*)(smem + A_P + 8192 + so0);
            b = *(const uint16_t*)(smem + A_P + 8192 + so1);
            *(uint32_t*)(smem + A_VT + 8192 + dd) = a | (b << 16);
        }

        // fixed-max softmax weights: p = 2^(s*SCL - M0), masked -> 0
        float p[32];
        #pragma unroll
        for (int j = 0; j < 32; j++)
            p[j] = exp2f(fmaf(__uint_as_float(r0[j]), SCL, -ATTN_M0));
        if (kt >= 2 * qt) {   // diagonal tiles: causal mask
            const int jbase = kt * 64 + half * 32;
            #pragma unroll
            for (int j = 0; j < 32; j++)
                if (jbase + j > grow) p[j] = 0.f;
        }
        #pragma unroll
        for (int j = 0; j < 32; j++) l += p[j];

        __syncthreads();   // S2: transpose reads done -> staging reusable as P

        // store this half's P (hi/lo), overwriting staging
        #pragma unroll
        for (int j8 = 0; j8 < 4; j8++) {
            __align__(16) __nv_bfloat16 hb[8], lb[8];
            #pragma unroll
            for (int j = 0; j < 8; j++) {
                const float v = p[(j8 << 3) + j];
                const __nv_bfloat16 h = __float2bfloat16(v);
                hb[j] = h;
                lb[j] = __float2bfloat16(v - __bfloat162float(h));
            }
            const int so = SMEM_SWIZZLE_128B((row << 7) | (half << 6) | (j8 << 4));
            *(uint4*)(smem + A_P + so)         = *(uint4*)hb;
            *(uint4*)(smem + A_P + 16384 + so) = *(uint4*)lb;
        }
        FENCE_PROXY_ASYNC();
        __syncthreads();   // S3: P + Vt visible

        if (wid == 0) {
            if (elect_one_pred()) {
                attn_issue_PV(tmem, sb, kt == kt0);
                TCGEN05_COMMIT(sb + A_MBAR1);
            }
            // issue S(kt+1) while PV(kt) runs (K loaded by this warp only)
            if (pre) {
                CP_WAIT_0();
                FENCE_PROXY_ASYNC();
                if (elect_one_pred()) {
                    attn_issue_S(tmem, sb);
                    TCGEN05_COMMIT(sb + A_MBAR0);
                }
            }
        }

        // PV(kt) done -> P region (V staging) and Vt reusable next tile
        MBARRIER_WAIT_PARITY(sb + A_MBAR1, it & 1);
    }

    // read partial O once; write fp32 partials + l
    TCGEN05_FENCE_AFTER();
    uint32_t po[32];
    TCGEN05_LD_X32(po, tmem + 64 + half * 32);
    TCGEN05_WAIT_LD();
    sls[half * 128 + row] = l;
    __syncthreads();
    {
        const long gofs = (long)spl * NTOK * DMODEL +
                          (tok0 + grow) * (long)DMODEL + head * 64 + half * 32;
        #pragma unroll
        for (int j4 = 0; j4 < 8; j4++) {
            float4 v = make_float4(__uint_as_float(po[j4 * 4 + 0]),
                                   __uint_as_float(po[j4 * 4 + 1]),
                                   __uint_as_float(po[j4 * 4 + 2]),
                                   __uint_as_float(po[j4 * 4 + 3]));
            *(float4*)&Op[gofs + j4 * 4] = v;
        }
        if (half == 0)
            lp[(long)spl * NTOK * NH + (tok0 + grow) * NH + head] =
                sls[row] + sls[128 + row];
    }
    __syncthreads();
    if (wid == 0) TCGEN05_DEALLOC(tmem, 128);

#else  // =================== compile-only FFMA fallback ===================
    if (tid < 128) {
        const int grow2 = qt * 128 + tid;
        const int kt0f = spl * (qt + 1);
        const int j0 = kt0f * 64;
        const int j1 = min((kt0f + qt + 1) * 64, grow2 + 1);
        const long qofs = (tok0 + grow2) * (long)QKVW + head * 64;
        float q[64], o2[64];
        #pragma unroll
        for (int c = 0; c < 64; c++) {
            q[c] = (__bfloat162float(qkv_hi[qofs + c]) +
                    __bfloat162float(qkv_lo[qofs + c])) * 0.125f;
            o2[c] = 0.f;
        }
        float l2 = 0.f;
        for (int j = j0; j < j1; j++) {
            const long kofs = (tok0 + j) * (long)QKVW + 1024 + head * 64;
            float s = 0.f;
            for (int c = 0; c < 64; c++)
                s += q[c] * (__bfloat162float(qkv_hi[kofs + c]) +
                             __bfloat162float(qkv_lo[kofs + c]));
            const float p = exp2f(s * 1.4426950408889634f - ATTN_M0);
            l2 += p;
            const long vofs = kofs + 1024;
            for (int c = 0; c < 64; c++)
                o2[c] += p * (__bfloat162float(qkv_hi[vofs + c]) +
                              __bfloat162float(qkv_lo[vofs + c]));
        }
        const long gofs = (long)spl * NTOK * DMODEL +
                          (tok0 + grow2) * (long)DMODEL + head * 64;
        for (int c = 0; c < 64; c++) Op[gofs + c] = o2[c];
        lp[(long)spl * NTOK * NH + (tok0 + grow2) * NH + head] = l2;
    }
#endif
}

// ================= split-KV combine: O=(O0+O1)/(l0+l1) -> bf16 hi/lo =================
__global__ __launch_bounds__(256) void attn_combine(const float* __restrict__ Op,
                                                    const float* __restrict__ lp,
                                                    __nv_bfloat16* __restrict__ ohi,
                                                    __nv_bfloat16* __restrict__ olo)
{
    const int tok = blockIdx.x;
    const int tid = threadIdx.x;
    const int c4  = tid * 4;                 // 4 cols per thread (1024 total)
    const int head = c4 >> 6;
    const float l0 = lp[(long)tok * NH + head];
    const float l1 = lp[(long)NTOK * NH + (long)tok * NH + head];
    const float invl = 1.0f / (l0 + l1);
    const long ofs = (long)tok * DMODEL + c4;
    float4 a = *(const float4*)&Op[ofs];
    float4 b = *(const float4*)&Op[(long)NTOK * DMODEL + ofs];
    split_store(ohi, olo, ofs + 0, (a.x + b.x) * invl);
    split_store(ohi, olo, ofs + 1, (a.y + b.y) * invl);
    split_store(ohi, olo, ofs + 2, (a.z + b.z) * invl);
    split_store(ohi, olo, ofs + 3, (a.w + b.w) * invl);
}

// ======================= driver =======================
extern "C" void kernel_launch(void* const* d_in, const int* in_sizes, int n_in,
                              void* d_out, int out_size)
{
    const float* x    = (const float*)d_in[0];
    const float* g1   = (const float*)d_in[1];
    const float* b1   = (const float*)d_in[2];
    const float* Wqkv = (const float*)d_in[3];
    const float* bqkv = (const float*)d_in[4];
    const float* Wo   = (const float*)d_in[5];
    const float* bo   = (const float*)d_in[6];
    const float* g2   = (const float*)d_in[7];
    const float* b2   = (const float*)d_in[8];
    const float* W1   = (const float*)d_in[9];
    const float* b1f  = (const float*)d_in[10];
    const float* W2   = (const float*)d_in[11];
    const float* b2f  = (const float*)d_in[12];
    float* out = (float*)d_out;

    float *x2, *Op, *lp;
    __nv_bfloat16 *qkv_hi, *qkv_lo;
    __nv_bfloat16 *h_hi, *h_lo, *attn_hi, *attn_lo, *hh_hi, *hh_lo, *ff_hi, *ff_lo;
    __nv_bfloat16 *WqkvT_hi, *WqkvT_lo, *WoT_hi, *WoT_lo, *W1T_hi, *W1T_lo, *W2T_hi, *W2T_lo;
    cudaGetSymbolAddress((void**)&x2,       g_x2);
    cudaGetSymbolAddress((void**)&Op,       g_Op);
    cudaGetSymbolAddress((void**)&lp,       g_lp);
    cudaGetSymbolAddress((void**)&qkv_hi,   g_qkv_hi);
    cudaGetSymbolAddress((void**)&qkv_lo,   g_qkv_lo);
    cudaGetSymbolAddress((void**)&h_hi,     g_h_hi);
    cudaGetSymbolAddress((void**)&h_lo,     g_h_lo);
    cudaGetSymbolAddress((void**)&attn_hi,  g_attn_hi);
    cudaGetSymbolAddress((void**)&attn_lo,  g_attn_lo);
    cudaGetSymbolAddress((void**)&hh_hi,    g_hh_hi);
    cudaGetSymbolAddress((void**)&hh_lo,    g_hh_lo);
    cudaGetSymbolAddress((void**)&ff_hi,    g_ff_hi);
    cudaGetSymbolAddress((void**)&ff_lo,    g_ff_lo);
    cudaGetSymbolAddress((void**)&WqkvT_hi, g_WqkvT_hi);
    cudaGetSymbolAddress((void**)&WqkvT_lo, g_WqkvT_lo);
    cudaGetSymbolAddress((void**)&WoT_hi,   g_WoT_hi);
    cudaGetSymbolAddress((void**)&WoT_lo,   g_WoT_lo);
    cudaGetSymbolAddress((void**)&W1T_hi,   g_W1T_hi);
    cudaGetSymbolAddress((void**)&W1T_lo,   g_W1T_lo);
    cudaGetSymbolAddress((void**)&W2T_hi,   g_W2T_hi);
    cudaGetSymbolAddress((void**)&W2T_lo,   g_W2T_lo);

    cudaFuncSetAttribute(attn_tc,         cudaFuncAttributeMaxDynamicSharedMemorySize, ATTN_SMEM);
    cudaFuncSetAttribute(gemm_tc<1, 256>, cudaFuncAttributeMaxDynamicSharedMemorySize, GEMM_SMEM);
    cudaFuncSetAttribute(gemm_tc<2, 128>, cudaFuncAttributeMaxDynamicSharedMemorySize, GEMM_SMEM);
    cudaFuncSetAttribute(gemm_tc<3, 256>, cudaFuncAttributeMaxDynamicSharedMemorySize, GEMM_SMEM);

    wtrans_kernel<<<dim3(QKVW / 64, DMODEL / 64), 256>>>(Wqkv, WqkvT_hi, WqkvT_lo, DMODEL, QKVW);
    ln_kernel<<<NTOK, 256>>>(x, g1, b1, h_hi, h_lo);
    // QKV projection -> bf16 hi/lo, N=256 tiles
    gemm_tc<3, 256><<<dim3(QKVW / 256, NTOK / 128), 256, GEMM_SMEM>>>(
        h_hi, h_lo, WqkvT_hi, WqkvT_lo, bqkv, nullptr, nullptr, qkv_hi, qkv_lo, QKVW, DMODEL);
    // causal attention (split-KV, fixed-max) -> fp32 partials, then combine
    attn_tc<<<dim3(2 * NQT, NH, BATCH), 256, ATTN_SMEM>>>(qkv_hi, qkv_lo, Op, lp);
    attn_combine<<<NTOK, 256>>>(Op, lp, attn_hi, attn_lo);
    wtrans_kernel<<<dim3(DMODEL / 64, DMODEL / 64), 256>>>(Wo, WoT_hi, WoT_lo, DMODEL, DMODEL);
    // output projection + residual -> x2 (fp32), N=128 tiles / 3-stage
    gemm_tc<2, 128><<<dim3(DMODEL / 128, NTOK / 128), 256, GEMM_SMEM>>>(
        attn_hi, attn_lo, WoT_hi, WoT_lo, bo, x, x2, nullptr, nullptr, DMODEL, DMODEL);
    ln_kernel<<<NTOK, 256>>>(x2, g2, b2, hh_hi, hh_lo);
    wtrans_kernel<<<dim3(FFDIM / 64, DMODEL / 64), 256>>>(W1, W1T_hi, W1T_lo, DMODEL, FFDIM);
    // FF1 + GELU -> hi/lo, N=256 tiles
    gemm_tc<1, 256><<<dim3(FFDIM / 256, NTOK / 128), 256, GEMM_SMEM>>>(
        hh_hi, hh_lo, W1T_hi, W1T_lo, b1f, nullptr, nullptr, ff_hi, ff_lo, FFDIM, DMODEL);
    wtrans_kernel<<<dim3(DMODEL / 64, FFDIM / 64), 256>>>(W2, W2T_hi, W2T_lo, FFDIM, DMODEL);
    // FF2 + residual -> out (fp32), N=128 tiles / 3-stage
    gemm_tc<2, 128><<<dim3(DMODEL / 128, NTOK / 128), 256, GEMM_SMEM>>>(
        ff_hi, ff_lo, W2T_hi, W2T_lo, b2f, x2, out, nullptr, nullptr, DMODEL, FFDIM);
}

// round 15
// speedup vs baseline: 1.0229x; 1.0229x over previous
#include <cuda_runtime.h>
#include <cuda_bf16.h>
#include <math.h>
#include <stdint.h>

// Problem dims (fixed by the reference)
#define NTOK   4096      // B*T = 2*2048
#define SEQ    2048
#define BATCH  2
#define DMODEL 1024
#define NH     16
#define HDIM   64
#define FFDIM  4096
#define QKVW   3072      // 3*DMODEL

// tcgen05 only exists in the arch-specific (sm_103a / sm_103f) compilation pass.
#if defined(__CUDA_ARCH__) && (__CUDA_ARCH__ == 1030) && \
    (defined(__CUDA_ARCH_FEAT_SM103_ALL) || defined(__CUDA_ARCH_SPECIFIC__) || \
     defined(__CUDA_ARCH_FAMILY_SPECIFIC__))
#define HAS_TCGEN05 1
#else
#define HAS_TCGEN05 0
#endif

// cp.async works on all passes (sm_80+)
#define CP_ASYNC16(smem_u32, gptr) \
    asm volatile("cp.async.cg.shared.global [%0], [%1], 16;" \
                 :: "r"((uint32_t)(smem_u32)), "l"(gptr) : "memory")
#define CP_COMMIT() asm volatile("cp.async.commit_group;" ::: "memory")
#define CP_WAIT_0() asm volatile("cp.async.wait_group 0;" ::: "memory")
#define CP_WAIT_1() asm volatile("cp.async.wait_group 1;" ::: "memory")

__device__ __forceinline__ uint32_t smem_u32_of(const void* p) {
    uint32_t a;
    asm("{ .reg .u64 t; cvta.to.shared.u64 t, %1; cvt.u32.u64 %0, t; }" : "=r"(a) : "l"(p));
    return a;
}

#if HAS_TCGEN05
// ======================= PTX helpers (arch-specific pass only) =======================
__device__ __forceinline__ uint32_t elect_one_pred() {
    uint32_t pred;
    asm volatile("{\n\t.reg .pred p;\n\telect.sync _|p, 0xFFFFFFFF;\n\tselp.b32 %0, 1, 0, p;\n\t}"
                 : "=r"(pred));
    return pred;
}

static constexpr uint64_t SMEM_DESC_BASE_SW128 =
    (uint64_t(2) << 61) | (uint64_t(1) << 46) | (uint64_t(64) << 32) | (uint64_t(1) << 16);
#define MAKE_SMEM_DESC(base_addr) \
    (SMEM_DESC_BASE_SW128 | ((uint64_t)((base_addr) >> 4) & 0x3FFF))

#define TCGEN05_ALLOC(sa, n) \
    asm volatile("tcgen05.alloc.cta_group::1.sync.aligned.shared::cta.b32 [%0], %1;" \
                 :: "r"((uint32_t)(sa)), "r"((uint32_t)(n)) : "memory")
#define TCGEN05_DEALLOC(t, n) \
    asm volatile("tcgen05.dealloc.cta_group::1.sync.aligned.b32 %0, %1;" :: "r"(t), "r"((uint32_t)(n)))
#define TCGEN05_RELINQUISH() \
    asm volatile("tcgen05.relinquish_alloc_permit.cta_group::1.sync.aligned;")
#define TCGEN05_COMMIT(mb) \
    asm volatile("tcgen05.commit.cta_group::1.mbarrier::arrive::one.shared::cluster.b64 [%0];" \
                 :: "r"((uint32_t)(mb)) : "memory")
#define TCGEN05_FENCE_AFTER() asm volatile("tcgen05.fence::after_thread_sync;" ::: "memory")
#define TCGEN05_WAIT_LD() asm volatile("tcgen05.wait::ld.sync.aligned;" ::: "memory")
#define FENCE_PROXY_ASYNC() asm volatile("fence.proxy.async.shared::cta;" ::: "memory")

#define MBARRIER_INIT(mb, cnt) \
    asm volatile("mbarrier.init.shared.b64 [%0], %1;" :: "r"((uint32_t)(mb)), "r"((uint32_t)(cnt)) : "memory")

#define MBARRIER_WAIT_PARITY(mb, par) do { \
    uint32_t _mb = (uint32_t)(mb), _p = (uint32_t)(par), _d; \
    asm volatile("{\n\t.reg .pred p;\n\t" \
        "mbarrier.try_wait.parity.acquire.cta.shared::cta.b64 p, [%1], %2;\n\t" \
        "selp.b32 %0, 1, 0, p;\n\t}" : "=r"(_d) : "r"(_mb), "r"(_p) : "memory"); \
    if (!_d) { \
        asm volatile("{\n\t.reg .pred P1;\n\t" \
            "WL_%=:\n\t" \
            "mbarrier.try_wait.parity.acquire.cta.shared::cta.b64 P1, [%0], %1, 0x989680;\n\t" \
            "@P1 bra.uni WD_%=;\n\t" \
            "bra.uni WL_%=;\n\t" \
            "WD_%=:\n\t}" :: "r"(_mb), "r"(_p) : "memory"); \
    } \
} while (0)

#define TCGEN05_LD_X32(r, ta) \
    asm volatile("tcgen05.ld.sync.aligned.32x32b.x32.b32 " \
        "{%0, %1, %2, %3, %4, %5, %6, %7, %8, %9, %10, %11, %12, %13, %14, %15, " \
        "%16, %17, %18, %19, %20, %21, %22, %23, %24, %25, %26, %27, %28, %29, %30, %31}, [%32];" \
        : "=r"((r)[0]), "=r"((r)[1]), "=r"((r)[2]), "=r"((r)[3]), \
          "=r"((r)[4]), "=r"((r)[5]), "=r"((r)[6]), "=r"((r)[7]), \
          "=r"((r)[8]), "=r"((r)[9]), "=r"((r)[10]), "=r"((r)[11]), \
          "=r"((r)[12]), "=r"((r)[13]), "=r"((r)[14]), "=r"((r)[15]), \
          "=r"((r)[16]), "=r"((r)[17]), "=r"((r)[18]), "=r"((r)[19]), \
          "=r"((r)[20]), "=r"((r)[21]), "=r"((r)[22]), "=r"((r)[23]), \
          "=r"((r)[24]), "=r"((r)[25]), "=r"((r)[26]), "=r"((r)[27]), \
          "=r"((r)[28]), "=r"((r)[29]), "=r"((r)[30]), "=r"((r)[31]) \
        : "r"(ta))

// cg1 kind::f16 SS-mode MMA (A and B both in SMEM, bf16 in / fp32 accum)
__device__ __forceinline__ void mma_f16_ss(uint32_t d, uint64_t ad, uint64_t bd,
                                           uint32_t idesc, bool acc) {
    uint32_t en = acc ? 1u : 0u;
    asm volatile(
        "{\n\t.reg .pred p;\n\tsetp.ne.u32 p, %5, 0;\n\t"
        "tcgen05.mma.cta_group::1.kind::f16 [%0], %1, %2, %3, {%4, %4, %4, %4}, p;\n\t}"
        :: "r"(d), "l"(ad), "l"(bd), "r"(idesc), "r"(0u), "r"(en) : "memory");
}

// idesc for attention MMAs: M=128, N=64, K-major both (validated in R4)
static constexpr uint32_t ATTN_IDESC =
    (1u << 4) | (1u << 7) | (1u << 10) | ((64u / 8u) << 17) | ((128u / 16u) << 24);
#endif  // HAS_TCGEN05

#define SMEM_SWIZZLE_128B(off) ((off) ^ (((off) >> 3) & 0x70))

// ======================= scratch (device globals) =======================
__device__ float g_x2  [NTOK * DMODEL];          // residual after attn proj
__device__ __nv_bfloat16 g_qkv_hi[NTOK * QKVW],  g_qkv_lo[NTOK * QKVW];
__device__ __nv_bfloat16 g_h_hi  [NTOK * DMODEL], g_h_lo  [NTOK * DMODEL];
__device__ __nv_bfloat16 g_attn_hi[NTOK * DMODEL], g_attn_lo[NTOK * DMODEL];
__device__ __nv_bfloat16 g_hh_hi [NTOK * DMODEL], g_hh_lo [NTOK * DMODEL];
__device__ __nv_bfloat16 g_ff_hi [NTOK * FFDIM],  g_ff_lo [NTOK * FFDIM];
__device__ __nv_bfloat16 g_WqkvT_hi[QKVW * DMODEL],  g_WqkvT_lo[QKVW * DMODEL];
__device__ __nv_bfloat16 g_WoT_hi [DMODEL * DMODEL], g_WoT_lo [DMODEL * DMODEL];
__device__ __nv_bfloat16 g_W1T_hi [FFDIM * DMODEL],  g_W1T_lo [FFDIM * DMODEL];
__device__ __nv_bfloat16 g_W2T_hi [DMODEL * FFDIM],  g_W2T_lo [DMODEL * FFDIM];

__device__ __forceinline__ void split_store(__nv_bfloat16* hi, __nv_bfloat16* lo,
                                            long ofs, float v) {
    __nv_bfloat16 h = __float2bfloat16(v);
    hi[ofs] = h;
    lo[ofs] = __float2bfloat16(v - __bfloat162float(h));
}
__device__ __forceinline__ uint32_t pack2bf(float a, float b) {
    __nv_bfloat162 t;
    t.x = __float2bfloat16(a);
    t.y = __float2bfloat16(b);
    return *(uint32_t*)&t;
}
__device__ __forceinline__ float gelu_exact(float x) {
    return 0.5f * x * (1.0f + erff(x * 0.70710678118654752f));
}

// ======================= LayerNorm -> bf16 hi/lo planes =======================
__global__ __launch_bounds__(256) void ln_kernel(const float* __restrict__ x,
                                                 const float* __restrict__ g,
                                                 const float* __restrict__ b,
                                                 __nv_bfloat16* __restrict__ yhi,
                                                 __nv_bfloat16* __restrict__ ylo)
{
    const int row = blockIdx.x;
    const int tid = threadIdx.x;
    const float* xr = x + (long)row * DMODEL;
    float4 v = *(const float4*)(xr + tid * 4);

    float s  = v.x + v.y + v.z + v.w;
    float sq = v.x*v.x + v.y*v.y + v.z*v.z + v.w*v.w;
    #pragma unroll
    for (int off = 16; off > 0; off >>= 1) {
        s  += __shfl_xor_sync(0xffffffffu, s,  off);
        sq += __shfl_xor_sync(0xffffffffu, sq, off);
    }
    __shared__ float reds[8], redq[8];
    const int wid = tid >> 5;
    if ((tid & 31) == 0) { reds[wid] = s; redq[wid] = sq; }
    __syncthreads();
    float st = 0.f, qt = 0.f;
    #pragma unroll
    for (int w = 0; w < 8; w++) { st += reds[w]; qt += redq[w]; }

    const float mu   = st * (1.0f / DMODEL);
    const float var  = qt * (1.0f / DMODEL) - mu * mu;
    const float rstd = rsqrtf(var + 1e-5f);

    float4 gv = *(const float4*)(g + tid * 4);
    float4 bv = *(const float4*)(b + tid * 4);
    float o0 = (v.x - mu) * rstd * gv.x + bv.x;
    float o1 = (v.y - mu) * rstd * gv.y + bv.y;
    float o2 = (v.z - mu) * rstd * gv.z + bv.z;
    float o3 = (v.w - mu) * rstd * gv.w + bv.w;
    const long base = (long)row * DMODEL + tid * 4;
    split_store(yhi, ylo, base + 0, o0);
    split_store(yhi, ylo, base + 1, o1);
    split_store(yhi, ylo, base + 2, o2);
    split_store(yhi, ylo, base + 3, o3);
}

// ============== weight transpose + bf16 hi/lo: W[K,N] -> T[N,K] (coalesced) ==============
__global__ __launch_bounds__(256) void wtrans_kernel(const float* __restrict__ W,
                                                     __nv_bfloat16* __restrict__ Thi,
                                                     __nv_bfloat16* __restrict__ Tlo,
                                                     int K, int N)
{
    __shared__ float tile[64][65];
    const int nb = blockIdx.x * 64;
    const int kb = blockIdx.y * 64;
    const int tid = threadIdx.x;
    #pragma unroll
    for (int i = 0; i < 4; i++) {
        const int idx = tid + i * 256;       // 0..1023
        const int k = idx >> 4;
        const int n4 = (idx & 15) << 2;
        float4 v = *(const float4*)&W[(long)(kb + k) * N + nb + n4];
        tile[k][n4 + 0] = v.x;
        tile[k][n4 + 1] = v.y;
        tile[k][n4 + 2] = v.z;
        tile[k][n4 + 3] = v.w;
    }
    __syncthreads();
    #pragma unroll
    for (int i = 0; i < 4; i++) {
        const int idx = tid + i * 256;       // 0..1023
        const int n  = idx >> 4;
        const int kq = (idx & 15) << 2;      // 4 consecutive K per thread
        float v0 = tile[kq + 0][n], v1 = tile[kq + 1][n];
        float v2 = tile[kq + 2][n], v3 = tile[kq + 3][n];
        const long ofs = (long)(nb + n) * K + kb + kq;
        uint2 hp, lp;
        hp.x = pack2bf(v0, v1); hp.y = pack2bf(v2, v3);
        __nv_bfloat162* h01 = (__nv_bfloat162*)&hp.x;
        __nv_bfloat162* h23 = (__nv_bfloat162*)&hp.y;
        lp.x = pack2bf(v0 - __bfloat162float(h01->x), v1 - __bfloat162float(h01->y));
        lp.y = pack2bf(v2 - __bfloat162float(h23->x), v3 - __bfloat162float(h23->y));
        *(uint2*)(Thi + ofs) = hp;
        *(uint2*)(Tlo + ofs) = lp;
    }
}

// ======================= GEMM (templated tile-N, cp.async pipeline) =======================
// C[M,N] = A[M,K] @ B[N,K]^T, bf16 hi/lo planes (K-major).
// TILE_N = 256 -> 2 stages; TILE_N = 128 -> 3 stages.
// OP: 1 = +bias, GELU -> bf16 hi/lo ; 2 = +bias +res -> fp32 ; 3 = +bias -> bf16 hi/lo
#define SM_TMEMPTR 0
#define SM_MBAR    16
#define SM_TILES   1024
#define GEMM_SMEM  197632      // 1024 + max(2*98304, 3*65536)

template<int OP, int TILE_N>
__global__ __launch_bounds__(256, 1) void gemm_tc(
    const __nv_bfloat16* __restrict__ Ahi, const __nv_bfloat16* __restrict__ Alo,
    const __nv_bfloat16* __restrict__ Bhi, const __nv_bfloat16* __restrict__ Blo,
    const float* __restrict__ bias, const float* __restrict__ res,
    float* __restrict__ Cf,
    __nv_bfloat16* __restrict__ Chi, __nv_bfloat16* __restrict__ Clo,
    int N, int K)
{
    extern __shared__ __align__(1024) char smem[];
    const int tid = threadIdx.x;
    const int mBase = blockIdx.y * 128;
    const int nBase = blockIdx.x * TILE_N;

    constexpr int NS = (TILE_N == 256) ? 2 : 3;
    constexpr int ST_AHI = 0;
    constexpr int ST_ALO = 16384;
    constexpr int ST_BHI = 32768;
    constexpr int ST_BLO = 32768 + TILE_N * 128;
    constexpr int STAGE_B = 32768 + TILE_N * 256;

#if HAS_TCGEN05
    const uint32_t smem_base = smem_u32_of(smem);
    const int wid = tid >> 5;
    const int lid = tid & 31;
    constexpr uint32_t IDESC =
        (1u << 4) | (1u << 7) | (1u << 10) | ((TILE_N / 8u) << 17) | (8u << 24);

    if (wid == 0) {
        TCGEN05_ALLOC(smem_base + SM_TMEMPTR, TILE_N);
        TCGEN05_RELINQUISH();
    }
    if (tid == 0) {
        #pragma unroll
        for (int i = 0; i < NS; i++)
            MBARRIER_INIT(smem_base + SM_MBAR + i * 8, 1);
    }
    __syncthreads();
    uint32_t tmem;
    asm volatile("ld.shared.b32 %0, [%1];" : "=r"(tmem) : "r"(smem_base + SM_TMEMPTR));

    auto load_chunk = [&](int c, int s) {
        const int k0 = c << 6;
        const __nv_bfloat16* srcAh = Ahi + (long)mBase * K + k0;
        const __nv_bfloat16* srcAl = Alo + (long)mBase * K + k0;
        const __nv_bfloat16* srcBh = Bhi + (long)nBase * K + k0;
        const __nv_bfloat16* srcBl = Blo + (long)nBase * K + k0;
        const uint32_t stage = smem_base + SM_TILES + s * STAGE_B;
        #pragma unroll
        for (int i = 0; i < 4; i++) {              // A: 128 rows
            const int idx = tid + i * 256;
            const int r   = idx >> 3;
            const int c16 = idx & 7;
            const long gofs = (long)r * K + (c16 << 3);
            const uint32_t sofs = stage + SMEM_SWIZZLE_128B((r << 7) | (c16 << 4));
            CP_ASYNC16(sofs + ST_AHI, srcAh + gofs);
            CP_ASYNC16(sofs + ST_ALO, srcAl + gofs);
        }
        #pragma unroll
        for (int i = 0; i < TILE_N / 32; i++) {    // B: TILE_N rows
            const int idx = tid + i * 256;
            const int r   = idx >> 3;
            const int c16 = idx & 7;
            const long gofs = (long)r * K + (c16 << 3);
            const uint32_t sofs = stage + SMEM_SWIZZLE_128B((r << 7) | (c16 << 4));
            CP_ASYNC16(sofs + ST_BHI, srcBh + gofs);
            CP_ASYNC16(sofs + ST_BLO, srcBl + gofs);
        }
        CP_COMMIT();
    };

    const int NC = K >> 6;   // K-chunks of 64 (>= 16 here)
    load_chunk(0, 0);
    load_chunk(1, 1);

    for (int c = 0; c < NC; c++) {
        const int s = c % NS;
        if (c + 1 < NC) CP_WAIT_1(); else CP_WAIT_0();
        FENCE_PROXY_ASYNC();
        __syncthreads();

        if (wid == 0) {
            const uint32_t stage = smem_base + SM_TILES + s * STAGE_B;
            const uint64_t dAhi = MAKE_SMEM_DESC(stage + ST_AHI);
            const uint64_t dAlo = MAKE_SMEM_DESC(stage + ST_ALO);
            const uint64_t dBhi = MAKE_SMEM_DESC(stage + ST_BHI);
            const uint64_t dBlo = MAKE_SMEM_DESC(stage + ST_BLO);
            if (elect_one_pred()) {
                #pragma unroll
                for (int kk = 0; kk < 4; kk++) {
                    mma_f16_ss(tmem, dAhi + kk * 2, dBhi + kk * 2, IDESC,
                               !(c == 0 && kk == 0));
                    mma_f16_ss(tmem, dAlo + kk * 2, dBhi + kk * 2, IDESC, true);
                    mma_f16_ss(tmem, dAhi + kk * 2, dBlo + kk * 2, IDESC, true);
                }
                TCGEN05_COMMIT(smem_base + SM_MBAR + s * 8);
            }
        }

        // prefetch chunk c+2 into stage (c+2)%NS (held chunk c+2-NS -> wait its MMA)
        if (c + 2 < NC) {
            const int prev = c + 2 - NS;
            if (prev >= 0)
                MBARRIER_WAIT_PARITY(smem_base + SM_MBAR + (prev % NS) * 8,
                                     ((prev / NS) & 1));
            load_chunk(c + 2, (c + 2) % NS);
        }
    }

    // wait for ALL MMAs (in-order pipe: last commit covers all prior)
    MBARRIER_WAIT_PARITY(smem_base + SM_MBAR + ((NC - 1) % NS) * 8, ((NC - 1) / NS) & 1);
    TCGEN05_FENCE_AFTER();

    // Epilogue: TILE_N/128 column-halves through the SMEM staging buffer
    float* sout = (float*)(smem + SM_TILES);
    #pragma unroll
    for (int h2 = 0; h2 < TILE_N / 128; h2++) {
        if (wid < 4) {
            const int r = (wid << 5) + lid;
            #pragma unroll
            for (int cb = 0; cb < 4; cb++) {
                uint32_t regs[32];
                TCGEN05_LD_X32(regs, tmem + h2 * 128 + (cb << 5));
                TCGEN05_WAIT_LD();
                #pragma unroll
                for (int j = 0; j < 32; j += 4) {
                    float4 v = make_float4(__uint_as_float(regs[j]),
                                           __uint_as_float(regs[j + 1]),
                                           __uint_as_float(regs[j + 2]),
                                           __uint_as_float(regs[j + 3]));
                    *(float4*)&sout[r * 132 + (cb << 5) + j] = v;
                }
            }
        }
        __syncthreads();

        for (int idx = tid; idx < 128 * 32; idx += 256) {
            const int r = idx >> 5;
            const int cc = (idx & 31) << 2;
            float4 v = *(float4*)&sout[r * 132 + cc];
            const long gr = mBase + r;
            const int  gc = nBase + h2 * 128 + cc;
            float4 bb = *(const float4*)&bias[gc];
            v.x += bb.x; v.y += bb.y; v.z += bb.z; v.w += bb.w;
            if (OP == 1 || OP == 3) {
                if (OP == 1) {
                    v.x = gelu_exact(v.x); v.y = gelu_exact(v.y);
                    v.z = gelu_exact(v.z); v.w = gelu_exact(v.w);
                }
                const long o = gr * N + gc;
                split_store(Chi, Clo, o + 0, v.x);
                split_store(Chi, Clo, o + 1, v.y);
                split_store(Chi, Clo, o + 2, v.z);
                split_store(Chi, Clo, o + 3, v.w);
            } else if (OP == 2) {
                float4 rr = *(const float4*)&res[gr * N + gc];
                v.x += rr.x; v.y += rr.y; v.z += rr.z; v.w += rr.w;
                *(float4*)&Cf[gr * N + gc] = v;
            } else {
                *(float4*)&Cf[gr * N + gc] = v;
            }
        }
        __syncthreads();
    }
    if (wid == 0) TCGEN05_DEALLOC(tmem, TILE_N);

#else  // =================== FFMA fallback (non-103a passes; never runs on GB300) ===================
    float* As = (float*)smem;                 // [8][128]
    float* Bs = As + 8 * 128;                 // [8][128]

    const int tx = tid & 15;
    const int ty = tid >> 4;
    const int row  = tid >> 1;                // 0..127
    const int kc   = (tid & 1) << 2;          // 0 or 4

    for (int h2 = 0; h2 < TILE_N / 128; h2++) {
        const int nB = nBase + h2 * 128;
        float acc[8][8];
        #pragma unroll
        for (int i = 0; i < 8; i++)
            #pragma unroll
            for (int j = 0; j < 8; j++) acc[i][j] = 0.f;

        for (int k0 = 0; k0 < K; k0 += 8) {
            {
                const long o = (long)(mBase + row) * K + k0 + kc;
                ushort4 h = *(const ushort4*)(Ahi + o);
                ushort4 l = *(const ushort4*)(Alo + o);
                As[(kc + 0) * 128 + row] = __bfloat162float(*(__nv_bfloat16*)&h.x) + __bfloat162float(*(__nv_bfloat16*)&l.x);
                As[(kc + 1) * 128 + row] = __bfloat162float(*(__nv_bfloat16*)&h.y) + __bfloat162float(*(__nv_bfloat16*)&l.y);
                As[(kc + 2) * 128 + row] = __bfloat162float(*(__nv_bfloat16*)&h.z) + __bfloat162float(*(__nv_bfloat16*)&l.z);
                As[(kc + 3) * 128 + row] = __bfloat162float(*(__nv_bfloat16*)&h.w) + __bfloat162float(*(__nv_bfloat16*)&l.w);
            }
            {
                const long o = (long)(nB + row) * K + k0 + kc;
                ushort4 h = *(const ushort4*)(Bhi + o);
                ushort4 l = *(const ushort4*)(Blo + o);
                Bs[(kc + 0) * 128 + row] = __bfloat162float(*(__nv_bfloat16*)&h.x) + __bfloat162float(*(__nv_bfloat16*)&l.x);
                Bs[(kc + 1) * 128 + row] = __bfloat162float(*(__nv_bfloat16*)&h.y) + __bfloat162float(*(__nv_bfloat16*)&l.y);
                Bs[(kc + 2) * 128 + row] = __bfloat162float(*(__nv_bfloat16*)&h.z) + __bfloat162float(*(__nv_bfloat16*)&l.z);
                Bs[(kc + 3) * 128 + row] = __bfloat162float(*(__nv_bfloat16*)&h.w) + __bfloat162float(*(__nv_bfloat16*)&l.w);
            }
            __syncthreads();

            #pragma unroll
            for (int k = 0; k < 8; k++) {
                float a[8], bb[8];
                #pragma unroll
                for (int i = 0; i < 8; i++) a[i]  = As[k * 128 + ty * 8 + i];
                #pragma unroll
                for (int j = 0; j < 8; j++) bb[j] = Bs[k * 128 + tx * 8 + j];
                #pragma unroll
                for (int i = 0; i < 8; i++)
                    #pragma unroll
                    for (int j = 0; j < 8; j++)
                        acc[i][j] = fmaf(a[i], bb[j], acc[i][j]);
            }
            __syncthreads();
        }

        #pragma unroll
        for (int i = 0; i < 8; i++) {
            const long gr = mBase + ty * 8 + i;
            #pragma unroll
            for (int j = 0; j < 8; j++) {
                const int gc = nB + tx * 8 + j;
                float v = acc[i][j] + bias[gc];
                if (OP == 1) {
                    v = gelu_exact(v);
                    split_store(Chi, Clo, gr * N + gc, v);
                } else if (OP == 3) {
                    split_store(Chi, Clo, gr * N + gc, v);
                } else if (OP == 2) {
                    Cf[gr * N + gc] = v + res[gr * N + gc];
                } else {
                    Cf[gr * N + gc] = v;
                }
            }
        }
        __syncthreads();
    }
#endif
}

// ======================= tcgen05 causal flash attention (fixed-max softmax) =======================
// 64-key tiles, 99 KB SMEM -> 2 CTAs/SM; p = exp2(s*SCL - M0) (offset cancels in
// O/l); O accumulates in TMEM across all tiles; single K buffer with warp-0
// prefetch; V staged into dead P region + in-SMEM transpose.
#define A_TMEMPTR 0
#define A_MBAR0   8
#define A_MBAR1   16
#define A_SLS     1056          // float[256]
#define A_Q       3072          // hi 16K, lo at +16384
#define A_K       35840         // hi 8K, lo at +8192
#define A_VT      52224         // hi 8K, lo at +8192
#define A_P       68608         // hi 16K, lo at +16384 ; V staging: hi +0, lo +8192
#define ATTN_SMEM 101376
#define ATTN_M0   20.0f

#if HAS_TCGEN05
__device__ __forceinline__ void attn_issue_S(uint32_t tmem, uint32_t sb) {
    const uint64_t dQh = MAKE_SMEM_DESC(sb + A_Q);
    const uint64_t dQl = MAKE_SMEM_DESC(sb + A_Q + 16384);
    const uint64_t dKh = MAKE_SMEM_DESC(sb + A_K);
    const uint64_t dKl = MAKE_SMEM_DESC(sb + A_K + 8192);
    #pragma unroll
    for (int kk = 0; kk < 4; kk++) {
        mma_f16_ss(tmem, dQh + kk * 2, dKh + kk * 2, ATTN_IDESC, kk != 0);
        mma_f16_ss(tmem, dQl + kk * 2, dKh + kk * 2, ATTN_IDESC, true);
        mma_f16_ss(tmem, dQh + kk * 2, dKl + kk * 2, ATTN_IDESC, true);
    }
}
__device__ __forceinline__ void attn_issue_PV(uint32_t tmem, uint32_t sb, bool first) {
    const uint64_t dPh = MAKE_SMEM_DESC(sb + A_P);
    const uint64_t dPl = MAKE_SMEM_DESC(sb + A_P + 16384);
    const uint64_t dVh = MAKE_SMEM_DESC(sb + A_VT);
    const uint64_t dVl = MAKE_SMEM_DESC(sb + A_VT + 8192);
    #pragma unroll
    for (int kk = 0; kk < 4; kk++) {
        mma_f16_ss(tmem + 64, dPh + kk * 2, dVh + kk * 2, ATTN_IDESC, !(first && kk == 0));
        mma_f16_ss(tmem + 64, dPl + kk * 2, dVh + kk * 2, ATTN_IDESC, true);
        mma_f16_ss(tmem + 64, dPh + kk * 2, dVl + kk * 2, ATTN_IDESC, true);
    }
}
#endif

__global__ __launch_bounds__(256, 2) void attn_tc(
    const __nv_bfloat16* __restrict__ qkv_hi,
    const __nv_bfloat16* __restrict__ qkv_lo,
    __nv_bfloat16* __restrict__ ohi,
    __nv_bfloat16* __restrict__ olo)
{
    extern __shared__ __align__(1024) char smem[];
    const int tid  = threadIdx.x;
    const int wid  = tid >> 5;
    const int lid  = tid & 31;
    const int qt   = gridDim.x - 1 - blockIdx.x;   // reversed: long CTAs first
    const int head = blockIdx.y;
    const int bat  = blockIdx.z;
    const long tok0 = (long)bat * SEQ;

#if HAS_TCGEN05
    const uint32_t sb = smem_u32_of(smem);
    float* sls = (float*)(smem + A_SLS);
    if (wid == 0) {
        TCGEN05_ALLOC(sb + A_TMEMPTR, 128);
        TCGEN05_RELINQUISH();
    }
    if (tid == 0) {
        MBARRIER_INIT(sb + A_MBAR0, 1);
        MBARRIER_INIT(sb + A_MBAR1, 1);
    }
    __syncthreads();
    uint32_t tmem;
    asm volatile("ld.shared.b32 %0, [%1];" : "=r"(tmem) : "r"(sb + A_TMEMPTR));

    // Q tile (128 x 64 hi/lo) + K tile 0 (64 keys) via cp.async
    #pragma unroll
    for (int i = 0; i < 4; i++) {
        const int idx = tid + i * 256;
        const int r = idx >> 3, c8 = idx & 7;
        const uint32_t sofs = SMEM_SWIZZLE_128B((r << 7) | (c8 << 4));
        const long gq = (tok0 + qt * 128 + r) * (long)QKVW + head * 64 + (c8 << 3);
        CP_ASYNC16(sb + A_Q + sofs,         qkv_hi + gq);
        CP_ASYNC16(sb + A_Q + 16384 + sofs, qkv_lo + gq);
    }
    #pragma unroll
    for (int i = 0; i < 2; i++) {
        const int idx = tid + i * 256;       // 0..511
        const int r = idx >> 3, c8 = idx & 7;
        const uint32_t sofs = SMEM_SWIZZLE_128B((r << 7) | (c8 << 4));
        const long gk = (tok0 + r) * (long)QKVW + 1024 + head * 64 + (c8 << 3);
        CP_ASYNC16(sb + A_K + sofs,        qkv_hi + gk);
        CP_ASYNC16(sb + A_K + 8192 + sofs, qkv_lo + gk);
    }
    CP_COMMIT();
    CP_WAIT_0();
    FENCE_PROXY_ASYNC();
    __syncthreads();
    if (wid == 0 && elect_one_pred()) {
        attn_issue_S(tmem, sb);
        TCGEN05_COMMIT(sb + A_MBAR0);
    }

    const int half = wid >> 2;                 // column half (32 key-cols / 32 hd-cols)
    const int row  = ((wid & 3) << 5) + lid;   // q row
    const int grow = qt * 128 + row;
    const int nkt  = 2 * qt + 2;
    const float SCL = 0.125f * 1.4426950408889634f;  // fold 1/sqrt(hd) * log2(e)

    float l = 0.f;

    for (int kt = 0; kt < nkt; kt++) {
        const bool pre = (kt + 1 < nkt);

        // stage V(kt) into P region (PV(kt-1) done: mb1 waited at prior loop end)
        #pragma unroll
        for (int i = 0; i < 2; i++) {
            const int idx = tid + i * 256;
            const int r = idx >> 3, c8 = idx & 7;
            const uint32_t sofs = SMEM_SWIZZLE_128B((r << 7) | (c8 << 4));
            const long gv = (tok0 + kt * 64 + r) * (long)QKVW + 2048 + head * 64 + (c8 << 3);
            CP_ASYNC16(sb + A_P + sofs,        qkv_hi + gv);
            CP_ASYNC16(sb + A_P + 8192 + sofs, qkv_lo + gv);
        }
        CP_COMMIT();   // group V (every thread)

        // wait S(kt) -> K buffer free -> K(kt+1) prefetch by warp 0 only
        MBARRIER_WAIT_PARITY(sb + A_MBAR0, kt & 1);
        TCGEN05_FENCE_AFTER();
        if (pre && wid == 0) {
            #pragma unroll
            for (int i = 0; i < 16; i++) {
                const int idx = lid + i * 32;      // 0..511
                const int r = idx >> 3, c8 = idx & 7;
                const uint32_t sofs = SMEM_SWIZZLE_128B((r << 7) | (c8 << 4));
                const long gk = (tok0 + (kt + 1) * 64 + r) * (long)QKVW + 1024 + head * 64 + (c8 << 3);
                CP_ASYNC16(sb + A_K + sofs,        qkv_hi + gk);
                CP_ASYNC16(sb + A_K + 8192 + sofs, qkv_lo + gk);
            }
            CP_COMMIT();   // group K (warp 0 threads only)
        }

        // pull this warp's 32 S columns
        uint32_t r0[32];
        TCGEN05_LD_X32(r0, tmem + half * 32);
        TCGEN05_WAIT_LD();

        // V staged complete (warp 0 may still have K in flight)
        if (pre && wid == 0) CP_WAIT_1(); else CP_WAIT_0();
        __syncthreads();   // S1: staged V visible

        // transpose staged V -> Vt[hd][key] (hi + lo)
        #pragma unroll
        for (int i = 0; i < 8; i++) {
            const int idx = tid + i * 256;        // 0..2047
            const int c  = idx & 63;              // hd
            const int kp = idx >> 6;              // key pair 0..31
            const int so0 = SMEM_SWIZZLE_128B(((2 * kp)     << 7) | (c << 1));
            const int so1 = SMEM_SWIZZLE_128B(((2 * kp + 1) << 7) | (c << 1));
            const int dd  = SMEM_SWIZZLE_128B((c << 7) | (kp << 2));
            uint32_t a = *(const uint16_t*)(smem + A_P + so0);
            uint32_t b = *(const uint16_t*)(smem + A_P + so1);
            *(uint32_t*)(smem + A_VT + dd) = a | (b << 16);
            a = *(const uint16_t*)(smem + A_P + 8192 + so0);
            b = *(const uint16_t*)(smem + A_P + 8192 + so1);
            *(uint32_t*)(smem + A_VT + 8192 + dd) = a | (b << 16);
        }

        // fixed-max softmax weights: p = 2^(s*SCL - M0), masked -> 0
        float p[32];
        #pragma unroll
        for (int j = 0; j < 32; j++)
            p[j] = exp2f(fmaf(__uint_as_float(r0[j]), SCL, -ATTN_M0));
        if (kt >= 2 * qt) {   // diagonal tiles: causal mask
            const int jbase = kt * 64 + half * 32;
            #pragma unroll
            for (int j = 0; j < 32; j++)
                if (jbase + j > grow) p[j] = 0.f;
        }
        #pragma unroll
        for (int j = 0; j < 32; j++) l += p[j];

        __syncthreads();   // S2: transpose reads done -> staging reusable as P

        // store this half's P (hi/lo), overwriting staging
        #pragma unroll
        for (int j8 = 0; j8 < 4; j8++) {
            __align__(16) __nv_bfloat16 hb[8], lb[8];
            #pragma unroll
            for (int j = 0; j < 8; j++) {
                const float v = p[(j8 << 3) + j];
                const __nv_bfloat16 h = __float2bfloat16(v);
                hb[j] = h;
                lb[j] = __float2bfloat16(v - __bfloat162float(h));
            }
            const int so = SMEM_SWIZZLE_128B((row << 7) | (half << 6) | (j8 << 4));
            *(uint4*)(smem + A_P + so)         = *(uint4*)hb;
            *(uint4*)(smem + A_P + 16384 + so) = *(uint4*)lb;
        }
        FENCE_PROXY_ASYNC();
        __syncthreads();   // S3: P + Vt visible

        if (wid == 0) {
            if (elect_one_pred()) {
                attn_issue_PV(tmem, sb, kt == 0);
                TCGEN05_COMMIT(sb + A_MBAR1);
            }
            // issue S(kt+1) while PV(kt) runs (K loaded by this warp only)
            if (pre) {
                CP_WAIT_0();
                FENCE_PROXY_ASYNC();
                if (elect_one_pred()) {
                    attn_issue_S(tmem, sb);
                    TCGEN05_COMMIT(sb + A_MBAR0);
                }
            }
        }

        // PV(kt) done -> P region (V staging) and Vt reusable next tile
        MBARRIER_WAIT_PARITY(sb + A_MBAR1, kt & 1);
    }

    // read O once; combine the two halves' l
    TCGEN05_FENCE_AFTER();
    uint32_t po[32];
    TCGEN05_LD_X32(po, tmem + 64 + half * 32);
    TCGEN05_WAIT_LD();
    sls[half * 128 + row] = l;
    __syncthreads();
    {
        const float invl = 1.0f / (sls[row] + sls[128 + row]);
        const long gofs = (tok0 + grow) * (long)DMODEL + head * 64 + half * 32;
        #pragma unroll
        for (int j8 = 0; j8 < 4; j8++) {
            __align__(16) __nv_bfloat16 hb[8], lb[8];
            #pragma unroll
            for (int j = 0; j < 8; j++) {
                const float v = __uint_as_float(po[(j8 << 3) + j]) * invl;
                const __nv_bfloat16 h = __float2bfloat16(v);
                hb[j] = h;
                lb[j] = __float2bfloat16(v - __bfloat162float(h));
            }
            *(uint4*)(ohi + gofs + (j8 << 3)) = *(uint4*)hb;
            *(uint4*)(olo + gofs + (j8 << 3)) = *(uint4*)lb;
        }
    }
    __syncthreads();
    if (wid == 0) TCGEN05_DEALLOC(tmem, 128);

#else  // =================== compile-only FFMA fallback ===================
    if (tid < 128) {
        const int grow2 = qt * 128 + tid;
        const long qofs = (tok0 + grow2) * (long)QKVW + head * 64;
        float q[64], o2[64];
        #pragma unroll
        for (int c = 0; c < 64; c++) {
            q[c] = (__bfloat162float(qkv_hi[qofs + c]) +
                    __bfloat162float(qkv_lo[qofs + c])) * 0.125f;
            o2[c] = 0.f;
        }
        float m2 = -1e30f, l2 = 0.f;
        for (int j = 0; j <= grow2; j++) {
            const long kofs = (tok0 + j) * (long)QKVW + 1024 + head * 64;
            float s = 0.f;
            for (int c = 0; c < 64; c++)
                s += q[c] * (__bfloat162float(qkv_hi[kofs + c]) +
                             __bfloat162float(qkv_lo[kofs + c]));
            const float mnew = fmaxf(m2, s);
            const float scf = expf(m2 - mnew);
            const float p = expf(s - mnew);
            l2 = l2 * scf + p;
            m2 = mnew;
            const long vofs = kofs + 1024;
            for (int c = 0; c < 64; c++)
                o2[c] = o2[c] * scf + p * (__bfloat162float(qkv_hi[vofs + c]) +
                                           __bfloat162float(qkv_lo[vofs + c]));
        }
        const long gofs = (tok0 + grow2) * (long)DMODEL + head * 64;
        for (int c = 0; c < 64; c++)
            split_store(ohi, olo, gofs + c, o2[c] / l2);
    }
#endif
}

// ======================= driver =======================
extern "C" void kernel_launch(void* const* d_in, const int* in_sizes, int n_in,
                              void* d_out, int out_size)
{
    const float* x    = (const float*)d_in[0];
    const float* g1   = (const float*)d_in[1];
    const float* b1   = (const float*)d_in[2];
    const float* Wqkv = (const float*)d_in[3];
    const float* bqkv = (const float*)d_in[4];
    const float* Wo   = (const float*)d_in[5];
    const float* bo   = (const float*)d_in[6];
    const float* g2   = (const float*)d_in[7];
    const float* b2   = (const float*)d_in[8];
    const float* W1   = (const float*)d_in[9];
    const float* b1f  = (const float*)d_in[10];
    const float* W2   = (const float*)d_in[11];
    const float* b2f  = (const float*)d_in[12];
    float* out = (float*)d_out;

    float *x2;
    __nv_bfloat16 *qkv_hi, *qkv_lo;
    __nv_bfloat16 *h_hi, *h_lo, *attn_hi, *attn_lo, *hh_hi, *hh_lo, *ff_hi, *ff_lo;
    __nv_bfloat16 *WqkvT_hi, *WqkvT_lo, *WoT_hi, *WoT_lo, *W1T_hi, *W1T_lo, *W2T_hi, *W2T_lo;
    cudaGetSymbolAddress((void**)&x2,       g_x2);
    cudaGetSymbolAddress((void**)&qkv_hi,   g_qkv_hi);
    cudaGetSymbolAddress((void**)&qkv_lo,   g_qkv_lo);
    cudaGetSymbolAddress((void**)&h_hi,     g_h_hi);
    cudaGetSymbolAddress((void**)&h_lo,     g_h_lo);
    cudaGetSymbolAddress((void**)&attn_hi,  g_attn_hi);
    cudaGetSymbolAddress((void**)&attn_lo,  g_attn_lo);
    cudaGetSymbolAddress((void**)&hh_hi,    g_hh_hi);
    cudaGetSymbolAddress((void**)&hh_lo,    g_hh_lo);
    cudaGetSymbolAddress((void**)&ff_hi,    g_ff_hi);
    cudaGetSymbolAddress((void**)&ff_lo,    g_ff_lo);
    cudaGetSymbolAddress((void**)&WqkvT_hi, g_WqkvT_hi);
    cudaGetSymbolAddress((void**)&WqkvT_lo, g_WqkvT_lo);
    cudaGetSymbolAddress((void**)&WoT_hi,   g_WoT_hi);
    cudaGetSymbolAddress((void**)&WoT_lo,   g_WoT_lo);
    cudaGetSymbolAddress((void**)&W1T_hi,   g_W1T_hi);
    cudaGetSymbolAddress((void**)&W1T_lo,   g_W1T_lo);
    cudaGetSymbolAddress((void**)&W2T_hi,   g_W2T_hi);
    cudaGetSymbolAddress((void**)&W2T_lo,   g_W2T_lo);

    cudaFuncSetAttribute(attn_tc,         cudaFuncAttributeMaxDynamicSharedMemorySize, ATTN_SMEM);
    cudaFuncSetAttribute(gemm_tc<1, 256>, cudaFuncAttributeMaxDynamicSharedMemorySize, GEMM_SMEM);
    cudaFuncSetAttribute(gemm_tc<2, 128>, cudaFuncAttributeMaxDynamicSharedMemorySize, GEMM_SMEM);
    cudaFuncSetAttribute(gemm_tc<3, 256>, cudaFuncAttributeMaxDynamicSharedMemorySize, GEMM_SMEM);

    // Stream fork: all 4 wtrans run on s2, overlapped with LN1/QKV/attention on
    // the main (legacy) stream. Created fresh each call (no statics; kernel_launch
    // is invoked only a handful of times). Graph capture supports cross-stream
    // event dependencies; everything joins back before the dependent GEMMs.
    cudaStream_t s2;
    cudaStreamCreateWithFlags(&s2, cudaStreamNonBlocking);
    cudaEvent_t evFork, evQ, evO, ev1, ev2;
    cudaEventCreateWithFlags(&evFork, cudaEventDisableTiming);
    cudaEventCreateWithFlags(&evQ,    cudaEventDisableTiming);
    cudaEventCreateWithFlags(&evO,    cudaEventDisableTiming);
    cudaEventCreateWithFlags(&ev1,    cudaEventDisableTiming);
    cudaEventCreateWithFlags(&ev2,    cudaEventDisableTiming);

    cudaEventRecord(evFork, 0);              // fork from legacy stream
    cudaStreamWaitEvent(s2, evFork, 0);
    wtrans_kernel<<<dim3(QKVW / 64, DMODEL / 64), 256, 0, s2>>>(Wqkv, WqkvT_hi, WqkvT_lo, DMODEL, QKVW);
    cudaEventRecord(evQ, s2);
    wtrans_kernel<<<dim3(DMODEL / 64, DMODEL / 64), 256, 0, s2>>>(Wo, WoT_hi, WoT_lo, DMODEL, DMODEL);
    cudaEventRecord(evO, s2);
    wtrans_kernel<<<dim3(FFDIM / 64, DMODEL / 64), 256, 0, s2>>>(W1, W1T_hi, W1T_lo, DMODEL, FFDIM);
    cudaEventRecord(ev1, s2);
    wtrans_kernel<<<dim3(DMODEL / 64, FFDIM / 64), 256, 0, s2>>>(W2, W2T_hi, W2T_lo, FFDIM, DMODEL);
    cudaEventRecord(ev2, s2);

    // main stream: LN1 overlaps wtrans
    ln_kernel<<<NTOK, 256>>>(x, g1, b1, h_hi, h_lo);
    cudaStreamWaitEvent(0, evQ, 0);          // need WqkvT
    // QKV projection -> bf16 hi/lo, N=256 tiles
    gemm_tc<3, 256><<<dim3(QKVW / 256, NTOK / 128), 256, GEMM_SMEM>>>(
        h_hi, h_lo, WqkvT_hi, WqkvT_lo, bqkv, nullptr, nullptr, qkv_hi, qkv_lo, QKVW, DMODEL);
    // causal attention (tcgen05, fixed-max softmax, TMEM-resident O)
    attn_tc<<<dim3(SEQ / 128, NH, BATCH), 256, ATTN_SMEM>>>(qkv_hi, qkv_lo, attn_hi, attn_lo);
    cudaStreamWaitEvent(0, evO, 0);          // need WoT
    // output projection + residual -> x2 (fp32), N=128 tiles / 3-stage
    gemm_tc<2, 128><<<dim3(DMODEL / 128, NTOK / 128), 256, GEMM_SMEM>>>(
        attn_hi, attn_lo, WoT_hi, WoT_lo, bo, x, x2, nullptr, nullptr, DMODEL, DMODEL);
    ln_kernel<<<NTOK, 256>>>(x2, g2, b2, hh_hi, hh_lo);
    cudaStreamWaitEvent(0, ev1, 0);          // need W1T
    // FF1 + GELU -> hi/lo, N=256 tiles
    gemm_tc<1, 256><<<dim3(FFDIM / 256, NTOK / 128), 256, GEMM_SMEM>>>(
        hh_hi, hh_lo, W1T_hi, W1T_lo, b1f, nullptr, nullptr, ff_hi, ff_lo, FFDIM, DMODEL);
    cudaStreamWaitEvent(0, ev2, 0);          // need W2T (joins s2 fully)
    // FF2 + residual -> out (fp32), N=128 tiles / 3-stage
    gemm_tc<2, 128><<<dim3(DMODEL / 128, NTOK / 128), 256, GEMM_SMEM>>>(
        ff_hi, ff_lo, W2T_hi, W2T_lo, b2f, x2, out, nullptr, nullptr, DMODEL, FFDIM);
}